// round 2
// baseline (speedup 1.0000x reference)
#include <cuda_runtime.h>

// Problem constants
#define BZ   16
#define SQ   2048
#define HD   768
#define EZ   128
#define NTAG 10
#define H3   2304
#define M_ALL (BZ * SQ)            // 32768
#define START_SIZE (M_ALL * NTAG)  // 327680
#define INV96 (1.0f / 96.0f)       // 1/(HEADS*sqrt(D)) = 1/(12*8)

// Scratch (allocation-free rule: static __device__ arrays)
__device__ float g_k[M_ALL * HD];      // k projection  [B*S, H]
__device__ float g_q[BZ * EZ * HD];    // q projection  [B*E, H]

// ---------------------------------------------------------------------------
// Shared 128x128x768 NT-GEMM tile engine.
// BM=BN=128, BK=16, 256 threads, 8x8 micro-tile. A and W both row-major [rows, 768];
// C[m][n] = sum_k A[m][k] * W[n][k].
// ---------------------------------------------------------------------------
__device__ __forceinline__ void mm_iter(
    const float* __restrict__ A0, const float* __restrict__ A1,
    const float* __restrict__ B0, const float* __restrict__ B1,
    float (*As)[132], float (*Bs)[132], float acc[8][8],
    int lr, int lc, int tx, int ty)
{
    for (int kt = 0; kt < HD; kt += 16) {
        float4 a0 = *(const float4*)(A0 + kt);
        float4 a1 = *(const float4*)(A1 + kt);
        float4 b0 = *(const float4*)(B0 + kt);
        float4 b1 = *(const float4*)(B1 + kt);
        As[lc + 0][lr]      = a0.x; As[lc + 1][lr]      = a0.y;
        As[lc + 2][lr]      = a0.z; As[lc + 3][lr]      = a0.w;
        As[lc + 0][lr + 64] = a1.x; As[lc + 1][lr + 64] = a1.y;
        As[lc + 2][lr + 64] = a1.z; As[lc + 3][lr + 64] = a1.w;
        Bs[lc + 0][lr]      = b0.x; Bs[lc + 1][lr]      = b0.y;
        Bs[lc + 2][lr]      = b0.z; Bs[lc + 3][lr]      = b0.w;
        Bs[lc + 0][lr + 64] = b1.x; Bs[lc + 1][lr + 64] = b1.y;
        Bs[lc + 2][lr + 64] = b1.z; Bs[lc + 3][lr + 64] = b1.w;
        __syncthreads();
#pragma unroll
        for (int kk = 0; kk < 16; ++kk) {
            float a[8], b[8];
            *(float4*)&a[0] = *(const float4*)&As[kk][ty * 8];
            *(float4*)&a[4] = *(const float4*)&As[kk][ty * 8 + 4];
            *(float4*)&b[0] = *(const float4*)&Bs[kk][tx * 8];
            *(float4*)&b[4] = *(const float4*)&Bs[kk][tx * 8 + 4];
#pragma unroll
            for (int i = 0; i < 8; ++i)
#pragma unroll
                for (int j = 0; j < 8; ++j)
                    acc[i][j] = fmaf(a[i], b[j], acc[i][j]);
        }
        __syncthreads();
    }
}

// ---------------------------------------------------------------------------
// Kernel 0: initialize start_logit region of d_out with o_b.
// ---------------------------------------------------------------------------
__global__ void init_start_kernel(float* __restrict__ out, const float* __restrict__ ob)
{
    int i = blockIdx.x * 256 + threadIdx.x;
    if (i < START_SIZE) out[i] = ob[i % NTAG];
}

// ---------------------------------------------------------------------------
// Kernel 1: fused GLU start head (u/v GEMMs + sigmoid gate + tag reduction,
// atomicAdd into start logits; g never hits HBM).
// ---------------------------------------------------------------------------
__global__ void __launch_bounds__(256) glu_kernel(
    const float* __restrict__ hid,
    const float* __restrict__ uw, const float* __restrict__ ub,
    const float* __restrict__ vw, const float* __restrict__ vb,
    const float* __restrict__ ow,
    float* __restrict__ out)
{
    extern __shared__ float sm[];
    float (*As)[132] = (float(*)[132])sm;
    float (*Bs)[132] = (float(*)[132])(sm + 16 * 132);
    float* us = sm + 32 * 132;               // 128 x 129 (padded)

    const int mb = blockIdx.y * 128;         // over B*S
    const int nb = blockIdx.x * 128;         // over 3H
    const int tid = threadIdx.x;
    const int tx = tid & 15, ty = tid >> 4;
    const int lr = tid >> 2, lc = (tid & 3) << 2;

    const float* A0 = hid + (mb + lr) * HD + lc;
    const float* A1 = hid + (mb + lr + 64) * HD + lc;

    float acc[8][8];
#pragma unroll
    for (int i = 0; i < 8; ++i)
#pragma unroll
        for (int j = 0; j < 8; ++j) acc[i][j] = 0.f;

    mm_iter(A0, A1, uw + (nb + lr) * HD + lc, uw + (nb + lr + 64) * HD + lc,
            As, Bs, acc, lr, lc, tx, ty);
#pragma unroll
    for (int i = 0; i < 8; ++i)
#pragma unroll
        for (int j = 0; j < 8; ++j) {
            float x = acc[i][j] + ub[nb + tx * 8 + j];
            us[(ty * 8 + i) * 129 + tx * 8 + j] = 1.f / (1.f + expf(-x));
            acc[i][j] = 0.f;
        }

    mm_iter(A0, A1, vw + (nb + lr) * HD + lc, vw + (nb + lr + 64) * HD + lc,
            As, Bs, acc, lr, lc, tx, ty);
#pragma unroll
    for (int i = 0; i < 8; ++i)
#pragma unroll
        for (int j = 0; j < 8; ++j) {
            int id = (ty * 8 + i) * 129 + tx * 8 + j;
            us[id] = us[id] * (acc[i][j] + vb[nb + tx * 8 + j]);
        }

    float* ows = sm;  // [10][128]
    for (int i = tid; i < NTAG * 128; i += 256)
        ows[i] = ow[(i >> 7) * H3 + nb + (i & 127)];
    __syncthreads();

    const int row = tid & 127;
    const int half = tid >> 7;
    float t10[NTAG];
#pragma unroll
    for (int t = 0; t < NTAG; ++t) t10[t] = 0.f;
    const float* gr = us + row * 129 + half * 64;
    const float* owr = ows + half * 64;
#pragma unroll 4
    for (int n = 0; n < 64; ++n) {
        float g = gr[n];
#pragma unroll
        for (int t = 0; t < NTAG; ++t)
            t10[t] = fmaf(g, owr[t * 128 + n], t10[t]);
    }
    float* so = out + (mb + row) * NTAG;
#pragma unroll
    for (int t = 0; t < NTAG; ++t) atomicAdd(so + t, t10[t]);
}

// ---------------------------------------------------------------------------
// Kernel 2: k projection  g_k = hidden @ k_w^T + k_b   [32768, 768]
// ---------------------------------------------------------------------------
__global__ void __launch_bounds__(256) kproj_kernel(
    const float* __restrict__ hid, const float* __restrict__ kw,
    const float* __restrict__ kb)
{
    __shared__ float As[16][132], Bs[16][132];
    const int mb = blockIdx.y * 128, nb = blockIdx.x * 128;
    const int tid = threadIdx.x;
    const int tx = tid & 15, ty = tid >> 4;
    const int lr = tid >> 2, lc = (tid & 3) << 2;
    float acc[8][8];
#pragma unroll
    for (int i = 0; i < 8; ++i)
#pragma unroll
        for (int j = 0; j < 8; ++j) acc[i][j] = 0.f;
    mm_iter(hid + (mb + lr) * HD + lc, hid + (mb + lr + 64) * HD + lc,
            kw + (nb + lr) * HD + lc, kw + (nb + lr + 64) * HD + lc,
            As, Bs, acc, lr, lc, tx, ty);
#pragma unroll
    for (int i = 0; i < 8; ++i) {
        int m = mb + ty * 8 + i;
#pragma unroll
        for (int j = 0; j < 8; ++j) {
            int n = nb + tx * 8 + j;
            g_k[m * HD + n] = acc[i][j] + kb[n];
        }
    }
}

// ---------------------------------------------------------------------------
// Kernel 3: gathered q projection. entity_start is int32 on the wire
// (JAX x64-disabled: the reference's astype(int64) is a silent no-op).
// ---------------------------------------------------------------------------
__global__ void __launch_bounds__(256) qproj_kernel(
    const float* __restrict__ hid, const float* __restrict__ qw,
    const float* __restrict__ qb, const int* __restrict__ ent)
{
    __shared__ float As[16][132], Bs[16][132];
    __shared__ int idxs[128];
    const int b = blockIdx.y, nb = blockIdx.x * 128;
    const int tid = threadIdx.x;
    const int tx = tid & 15, ty = tid >> 4;
    const int lr = tid >> 2, lc = (tid & 3) << 2;
    if (tid < 128) idxs[tid] = ent[b * EZ + tid];
    __syncthreads();
    float acc[8][8];
#pragma unroll
    for (int i = 0; i < 8; ++i)
#pragma unroll
        for (int j = 0; j < 8; ++j) acc[i][j] = 0.f;
    const float* A0 = hid + ((long)b * SQ + idxs[lr]) * HD + lc;
    const float* A1 = hid + ((long)b * SQ + idxs[lr + 64]) * HD + lc;
    mm_iter(A0, A1, qw + (nb + lr) * HD + lc, qw + (nb + lr + 64) * HD + lc,
            As, Bs, acc, lr, lc, tx, ty);
#pragma unroll
    for (int i = 0; i < 8; ++i) {
        int m = b * EZ + ty * 8 + i;
#pragma unroll
        for (int j = 0; j < 8; ++j) {
            int n = nb + tx * 8 + j;
            g_q[m * HD + n] = acc[i][j] + qb[n];
        }
    }
}

// ---------------------------------------------------------------------------
// Kernel 4: end logits. Mask is int32 on the wire (bool -> int32).
// ---------------------------------------------------------------------------
__global__ void __launch_bounds__(256) end_kernel(
    const int* __restrict__ mask, float* __restrict__ out)
{
    __shared__ float As[16][132], Bs[16][132];
    const int b = blockIdx.y, nb = blockIdx.x * 128;  // nb over S
    const int tid = threadIdx.x;
    const int tx = tid & 15, ty = tid >> 4;
    const int lr = tid >> 2, lc = (tid & 3) << 2;
    float acc[8][8];
#pragma unroll
    for (int i = 0; i < 8; ++i)
#pragma unroll
        for (int j = 0; j < 8; ++j) acc[i][j] = 0.f;
    const float* A = g_q + (long)b * EZ * HD;
    const float* Bm = g_k + ((long)b * SQ + nb) * HD;
    mm_iter(A + lr * HD + lc, A + (lr + 64) * HD + lc,
            Bm + lr * HD + lc, Bm + (lr + 64) * HD + lc,
            As, Bs, acc, lr, lc, tx, ty);
    float* o = out + START_SIZE + (long)b * EZ * SQ;
    const int* mrow = mask + b * SQ;
#pragma unroll
    for (int i = 0; i < 8; ++i) {
        int e = ty * 8 + i;
#pragma unroll
        for (int j = 0; j < 8; ++j) {
            int s = nb + tx * 8 + j;
            float v = acc[i][j] * INV96;
            if (mrow[s] == 0) v = -50000.f;
            o[e * SQ + s] = v;
        }
    }
}

// ---------------------------------------------------------------------------
// Launch
// ---------------------------------------------------------------------------
extern "C" void kernel_launch(void* const* d_in, const int* in_sizes, int n_in,
                              void* d_out, int out_size)
{
    const float* hid  = (const float*)d_in[0];
    const float* uw   = (const float*)d_in[1];
    const float* ub   = (const float*)d_in[2];
    const float* vw   = (const float*)d_in[3];
    const float* vb   = (const float*)d_in[4];
    const float* ow   = (const float*)d_in[5];
    const float* ob   = (const float*)d_in[6];
    const float* qw   = (const float*)d_in[7];
    const float* qb   = (const float*)d_in[8];
    const float* kw   = (const float*)d_in[9];
    const float* kb   = (const float*)d_in[10];
    const int*   ent  = (const int*)d_in[11];
    const int*   mask = (const int*)d_in[12];
    float* out = (float*)d_out;

    const int GLU_SMEM = (16 * 132 * 2 + 128 * 129) * 4;  // 82944 B
    cudaFuncSetAttribute(glu_kernel, cudaFuncAttributeMaxDynamicSharedMemorySize, GLU_SMEM);

    init_start_kernel<<<(START_SIZE + 255) / 256, 256>>>(out, ob);
    glu_kernel<<<dim3(H3 / 128, M_ALL / 128), 256, GLU_SMEM>>>(hid, uw, ub, vw, vb, ow, out);
    kproj_kernel<<<dim3(HD / 128, M_ALL / 128), 256>>>(hid, kw, kb);
    qproj_kernel<<<dim3(HD / 128, BZ), 256>>>(hid, qw, qb, ent);
    end_kernel<<<dim3(SQ / 128, BZ), 256>>>(mask, out);
}

// round 4
// speedup vs baseline: 2.5411x; 2.5411x over previous
#include <cuda_runtime.h>

// ---------------------------------------------------------------------------
// Problem constants
// ---------------------------------------------------------------------------
#define BZ   16
#define SQ   2048
#define HD   768
#define EZ   128
#define NTAG 10
#define H3   2304
#define M_ALL (BZ * SQ)            // 32768
#define START_SIZE (M_ALL * NTAG)  // 327680
#define INV96 (1.0f / 96.0f)
#define KTILES 24                  // 768 / 32

// Scratch
__device__ float g_k[M_ALL * HD];
__device__ float g_q[BZ * EZ * HD];

// ---------------------------------------------------------------------------
// PTX helpers (baseline compute_100: cp.async + mma.sync tf32 only)
// ---------------------------------------------------------------------------
__device__ __forceinline__ unsigned s2u(const void* p) {
    unsigned a;
    asm("{ .reg .u64 t; cvta.to.shared.u64 t, %1; cvt.u32.u64 %0, t; }"
        : "=r"(a) : "l"(p));
    return a;
}
__device__ __forceinline__ unsigned rna(float x) {
    unsigned r;
    asm("cvt.rna.tf32.f32 %0, %1;" : "=r"(r) : "f"(x));
    return r;
}
__device__ __forceinline__ float lds32(unsigned a) {
    float v;
    asm volatile("ld.shared.f32 %0, [%1];" : "=f"(v) : "r"(a));
    return v;
}
__device__ __forceinline__ void cpa16(unsigned d, const float* s) {
    asm volatile("cp.async.cg.shared.global [%0], [%1], 16;" :: "r"(d), "l"(s));
}
__device__ __forceinline__ void mma8(float d[4], unsigned a0, unsigned a1,
                                     unsigned a2, unsigned a3,
                                     unsigned b0, unsigned b1) {
    asm volatile(
        "mma.sync.aligned.m16n8k8.row.col.f32.tf32.tf32.f32 "
        "{%0,%1,%2,%3}, {%4,%5,%6,%7}, {%8,%9}, {%0,%1,%2,%3};"
        : "+f"(d[0]), "+f"(d[1]), "+f"(d[2]), "+f"(d[3])
        : "r"(a0), "r"(a1), "r"(a2), "r"(a3), "r"(b0), "r"(b1));
}

// ---------------------------------------------------------------------------
// Core: C(128x128) += A(128x768) . B(128x768)^T  via tf32 mma.sync.
// 256 threads, warp grid 2(M) x 4(N), warp tile 64x32.
// Smem pipeline: 2 stages x (A[128][36] + B[128][36]) floats = 73728 B at smu.
// A passed as 4 per-thread row pointers (supports gather); B as one base
// pointer (rows tid/8 + 32j, stride HD).
// ---------------------------------------------------------------------------
__device__ __forceinline__ void gemm_tf32(
    unsigned smu,
    const float* a0, const float* a1, const float* a2, const float* a3,
    const float* b0,
    float acc[4][4][4], int tid)
{
    const int lane = tid & 31, warp = tid >> 5;
    const int wm = warp & 1, wn = warp >> 1;
    const int r = lane >> 2, cc = lane & 3;
    const unsigned dA = smu + (unsigned)(((tid >> 3) * 36 + (tid & 7) * 4) * 4);
    const unsigned dB = dA + 18432u;
    const float* asrc[4] = {a0, a1, a2, a3};

    unsigned aRow[4], bRow[4];
#pragma unroll
    for (int mi = 0; mi < 4; ++mi) aRow[mi] = (unsigned)((wm * 64 + mi * 16 + r) * 144);
#pragma unroll
    for (int ni = 0; ni < 4; ++ni) bRow[ni] = (unsigned)((wn * 32 + ni * 8 + r) * 144 + 18432);

    auto LOAD = [&](int s, int kt) {
        unsigned off = (unsigned)s * 36864u;
        int ko = kt * 32;
#pragma unroll
        for (int j = 0; j < 4; ++j) {
            cpa16(dA + off + j * 4608u, asrc[j] + ko);
            cpa16(dB + off + j * 4608u, b0 + (size_t)j * 32 * HD + ko);
        }
        asm volatile("cp.async.commit_group;" ::: "memory");
    };

    LOAD(0, 0);
    for (int kt = 0; kt < KTILES; ++kt) {
        if (kt < KTILES - 1) {
            LOAD((kt + 1) & 1, kt + 1);
            asm volatile("cp.async.wait_group 1;" ::: "memory");
        } else {
            asm volatile("cp.async.wait_group 0;" ::: "memory");
        }
        __syncthreads();
        unsigned base = smu + (unsigned)(kt & 1) * 36864u;
#pragma unroll
        for (int k8 = 0; k8 < 4; ++k8) {
            unsigned ko = (unsigned)((k8 * 8 + cc) * 4);
            unsigned a[4][4];
#pragma unroll
            for (int mi = 0; mi < 4; ++mi) {
                unsigned p = base + aRow[mi] + ko;
                a[mi][0] = rna(lds32(p));
                a[mi][1] = rna(lds32(p + 8 * 144));
                a[mi][2] = rna(lds32(p + 16));
                a[mi][3] = rna(lds32(p + 8 * 144 + 16));
            }
#pragma unroll
            for (int ni = 0; ni < 4; ++ni) {
                unsigned p = base + bRow[ni] + ko;
                unsigned bb0 = rna(lds32(p)), bb1 = rna(lds32(p + 16));
#pragma unroll
                for (int mi = 0; mi < 4; ++mi)
                    mma8(acc[mi][ni], a[mi][0], a[mi][1], a[mi][2], a[mi][3], bb0, bb1);
            }
        }
        __syncthreads();
    }
}

#define ZERO_ACC(acc) \
    _Pragma("unroll") for (int _i = 0; _i < 4; ++_i) \
    _Pragma("unroll") for (int _j = 0; _j < 4; ++_j) \
    _Pragma("unroll") for (int _q = 0; _q < 4; ++_q) acc[_i][_j][_q] = 0.f;

// ---------------------------------------------------------------------------
// Kernel 0: init start logits with o_b (GLU atomically accumulates on top)
// ---------------------------------------------------------------------------
__global__ void init_start_kernel(float* __restrict__ out, const float* __restrict__ ob)
{
    int i = blockIdx.x * 256 + threadIdx.x;
    if (i < START_SIZE) out[i] = ob[i % NTAG];
}

// ---------------------------------------------------------------------------
// Kernel 1: fused GLU start head. Two tf32 GEMM passes (u then v) sharing A;
// sigma(u) gate kept in smem; tag reduction + atomicAdd epilogue.
// Smem floats: [0,18432) pipeline, [18432,35328) us 128x132,
// [35328,36608) ow_s, [36608,36736) ub_s, [36736,36864) vb_s. 147456 B.
// ---------------------------------------------------------------------------
__global__ void __launch_bounds__(256) glu_mma_kernel(
    const float* __restrict__ hid,
    const float* __restrict__ uw, const float* __restrict__ ub,
    const float* __restrict__ vw, const float* __restrict__ vb,
    const float* __restrict__ ow,
    float* __restrict__ out)
{
    extern __shared__ float sm[];
    const unsigned smu = s2u(sm);
    float* us   = sm + 18432;
    float* ow_s = sm + 35328;
    float* ub_s = sm + 36608;
    float* vb_s = sm + 36736;

    const int tid = threadIdx.x;
    const int nb = blockIdx.x * 128, mb = blockIdx.y * 128;

    for (int i = tid; i < NTAG * 128; i += 256)
        ow_s[i] = ow[(i >> 7) * H3 + nb + (i & 127)];
    if (tid < 128) { ub_s[tid] = ub[nb + tid]; vb_s[tid] = vb[nb + tid]; }

    const int arow = tid >> 3, kch = tid & 7;
    const float* ha[4];
#pragma unroll
    for (int j = 0; j < 4; ++j)
        ha[j] = hid + (size_t)(mb + arow + 32 * j) * HD + kch * 4;
    const float* bu = uw + (size_t)(nb + arow) * HD + kch * 4;
    const float* bv = vw + (size_t)(nb + arow) * HD + kch * 4;

    const int lane = tid & 31, warp = tid >> 5;
    const int wm = warp & 1, wn = warp >> 1;
    const int r = lane >> 2, cc = lane & 3;

    float acc[4][4][4];
    ZERO_ACC(acc);
    gemm_tf32(smu, ha[0], ha[1], ha[2], ha[3], bu, acc, tid);

    // sigma(u + ub) -> us
#pragma unroll
    for (int mi = 0; mi < 4; ++mi) {
        int row = wm * 64 + mi * 16 + r;
#pragma unroll
        for (int ni = 0; ni < 4; ++ni) {
            int col = wn * 32 + ni * 8 + 2 * cc;
            float x0 = acc[mi][ni][0] + ub_s[col];
            float x1 = acc[mi][ni][1] + ub_s[col + 1];
            float x2 = acc[mi][ni][2] + ub_s[col];
            float x3 = acc[mi][ni][3] + ub_s[col + 1];
            us[row * 132 + col]       = 1.f / (1.f + __expf(-x0));
            us[row * 132 + col + 1]   = 1.f / (1.f + __expf(-x1));
            us[(row + 8) * 132 + col]     = 1.f / (1.f + __expf(-x2));
            us[(row + 8) * 132 + col + 1] = 1.f / (1.f + __expf(-x3));
        }
    }

    ZERO_ACC(acc);
    gemm_tf32(smu, ha[0], ha[1], ha[2], ha[3], bv, acc, tid);

    // g = sigma(u) * (v + vb) -> us (same positions, self-written)
#pragma unroll
    for (int mi = 0; mi < 4; ++mi) {
        int row = wm * 64 + mi * 16 + r;
#pragma unroll
        for (int ni = 0; ni < 4; ++ni) {
            int col = wn * 32 + ni * 8 + 2 * cc;
            us[row * 132 + col]           *= acc[mi][ni][0] + vb_s[col];
            us[row * 132 + col + 1]       *= acc[mi][ni][1] + vb_s[col + 1];
            us[(row + 8) * 132 + col]     *= acc[mi][ni][2] + vb_s[col];
            us[(row + 8) * 132 + col + 1] *= acc[mi][ni][3] + vb_s[col + 1];
        }
    }
    __syncthreads();

    // tag reduction + atomicAdd (proven epilogue; stride 132)
    {
        const int row = tid & 127, half = tid >> 7;
        float t10[NTAG];
#pragma unroll
        for (int t = 0; t < NTAG; ++t) t10[t] = 0.f;
        const float* gr = us + row * 132 + half * 64;
        const float* owr = ow_s + half * 64;
#pragma unroll 4
        for (int n = 0; n < 64; ++n) {
            float g = gr[n];
#pragma unroll
            for (int t = 0; t < NTAG; ++t)
                t10[t] = fmaf(g, owr[t * 128 + n], t10[t]);
        }
        float* so = out + (size_t)(mb + row) * NTAG;
#pragma unroll
        for (int t = 0; t < NTAG; ++t) atomicAdd(so + t, t10[t]);
    }
}

// ---------------------------------------------------------------------------
// Kernel 2: k projection  g_k = hid @ kw^T + kb
// ---------------------------------------------------------------------------
__global__ void __launch_bounds__(256) kproj_mma_kernel(
    const float* __restrict__ hid, const float* __restrict__ kw,
    const float* __restrict__ kb)
{
    extern __shared__ float sm[];
    const unsigned smu = s2u(sm);
    float* kb_s = sm + 18432;
    const int tid = threadIdx.x;
    const int nb = blockIdx.x * 128, mb = blockIdx.y * 128;
    if (tid < 128) kb_s[tid] = kb[nb + tid];

    const int arow = tid >> 3, kch = tid & 7;
    const float* ha[4];
#pragma unroll
    for (int j = 0; j < 4; ++j)
        ha[j] = hid + (size_t)(mb + arow + 32 * j) * HD + kch * 4;
    const float* bk = kw + (size_t)(nb + arow) * HD + kch * 4;

    float acc[4][4][4];
    ZERO_ACC(acc);
    gemm_tf32(smu, ha[0], ha[1], ha[2], ha[3], bk, acc, tid);

    const int lane = tid & 31, warp = tid >> 5;
    const int wm = warp & 1, wn = warp >> 1;
    const int r = lane >> 2, cc = lane & 3;
#pragma unroll
    for (int mi = 0; mi < 4; ++mi) {
        int row = wm * 64 + mi * 16 + r;
#pragma unroll
        for (int ni = 0; ni < 4; ++ni) {
            int col = wn * 32 + ni * 8 + 2 * cc;
            float2 w0 = { acc[mi][ni][0] + kb_s[col], acc[mi][ni][1] + kb_s[col + 1] };
            float2 w1 = { acc[mi][ni][2] + kb_s[col], acc[mi][ni][3] + kb_s[col + 1] };
            *(float2*)(g_k + (size_t)(mb + row) * HD + nb + col) = w0;
            *(float2*)(g_k + (size_t)(mb + row + 8) * HD + nb + col) = w1;
        }
    }
}

// ---------------------------------------------------------------------------
// Kernel 3: gathered q projection (entity_start int32)
// ---------------------------------------------------------------------------
__global__ void __launch_bounds__(256) qproj_mma_kernel(
    const float* __restrict__ hid, const float* __restrict__ qw,
    const float* __restrict__ qb, const int* __restrict__ ent)
{
    extern __shared__ float sm[];
    const unsigned smu = s2u(sm);
    float* qb_s = sm + 18432;
    int* idxs = (int*)(sm + 18560);
    const int tid = threadIdx.x;
    const int nb = blockIdx.x * 128, b = blockIdx.y;
    if (tid < 128) { qb_s[tid] = qb[nb + tid]; idxs[tid] = ent[b * EZ + tid]; }
    __syncthreads();

    const int arow = tid >> 3, kch = tid & 7;
    const float* ha[4];
#pragma unroll
    for (int j = 0; j < 4; ++j)
        ha[j] = hid + ((size_t)b * SQ + idxs[arow + 32 * j]) * HD + kch * 4;
    const float* bq = qw + (size_t)(nb + arow) * HD + kch * 4;

    float acc[4][4][4];
    ZERO_ACC(acc);
    gemm_tf32(smu, ha[0], ha[1], ha[2], ha[3], bq, acc, tid);

    const int lane = tid & 31, warp = tid >> 5;
    const int wm = warp & 1, wn = warp >> 1;
    const int r = lane >> 2, cc = lane & 3;
#pragma unroll
    for (int mi = 0; mi < 4; ++mi) {
        int row = wm * 64 + mi * 16 + r;
#pragma unroll
        for (int ni = 0; ni < 4; ++ni) {
            int col = wn * 32 + ni * 8 + 2 * cc;
            float2 w0 = { acc[mi][ni][0] + qb_s[col], acc[mi][ni][1] + qb_s[col + 1] };
            float2 w1 = { acc[mi][ni][2] + qb_s[col], acc[mi][ni][3] + qb_s[col + 1] };
            *(float2*)(g_q + ((size_t)b * EZ + row) * HD + nb + col) = w0;
            *(float2*)(g_q + ((size_t)b * EZ + row + 8) * HD + nb + col) = w1;
        }
    }
}

// ---------------------------------------------------------------------------
// Kernel 4: end logits = (q . k)/96, masked (mask int32)
// ---------------------------------------------------------------------------
__global__ void __launch_bounds__(256) end_mma_kernel(
    const int* __restrict__ mask, float* __restrict__ out)
{
    extern __shared__ float sm[];
    const unsigned smu = s2u(sm);
    int* mask_s = (int*)(sm + 18432);
    const int tid = threadIdx.x;
    const int nb = blockIdx.x * 128, b = blockIdx.y;   // nb over S
    if (tid < 128) mask_s[tid] = mask[b * SQ + nb + tid];
    __syncthreads();

    const int arow = tid >> 3, kch = tid & 7;
    const float* ha[4];
#pragma unroll
    for (int j = 0; j < 4; ++j)
        ha[j] = g_q + ((size_t)b * EZ + arow + 32 * j) * HD + kch * 4;
    const float* bk = g_k + ((size_t)b * SQ + nb + arow) * HD + kch * 4;

    float acc[4][4][4];
    ZERO_ACC(acc);
    gemm_tf32(smu, ha[0], ha[1], ha[2], ha[3], bk, acc, tid);

    const int lane = tid & 31, warp = tid >> 5;
    const int wm = warp & 1, wn = warp >> 1;
    const int r = lane >> 2, cc = lane & 3;
    float* ob = out + START_SIZE + (size_t)b * EZ * SQ;
#pragma unroll
    for (int mi = 0; mi < 4; ++mi) {
        int row = wm * 64 + mi * 16 + r;
#pragma unroll
        for (int ni = 0; ni < 4; ++ni) {
            int col = wn * 32 + ni * 8 + 2 * cc;
            int m0 = mask_s[col], m1 = mask_s[col + 1];
            float2 w0 = { m0 ? acc[mi][ni][0] * INV96 : -50000.f,
                          m1 ? acc[mi][ni][1] * INV96 : -50000.f };
            float2 w1 = { m0 ? acc[mi][ni][2] * INV96 : -50000.f,
                          m1 ? acc[mi][ni][3] * INV96 : -50000.f };
            *(float2*)(ob + (size_t)row * SQ + nb + col) = w0;
            *(float2*)(ob + (size_t)(row + 8) * SQ + nb + col) = w1;
        }
    }
}

// ---------------------------------------------------------------------------
// Launch
// ---------------------------------------------------------------------------
extern "C" void kernel_launch(void* const* d_in, const int* in_sizes, int n_in,
                              void* d_out, int out_size)
{
    const float* hid  = (const float*)d_in[0];
    const float* uw   = (const float*)d_in[1];
    const float* ub   = (const float*)d_in[2];
    const float* vw   = (const float*)d_in[3];
    const float* vb   = (const float*)d_in[4];
    const float* ow   = (const float*)d_in[5];
    const float* ob   = (const float*)d_in[6];
    const float* qw   = (const float*)d_in[7];
    const float* qb   = (const float*)d_in[8];
    const float* kw   = (const float*)d_in[9];
    const float* kb   = (const float*)d_in[10];
    const int*   ent  = (const int*)d_in[11];
    const int*   mask = (const int*)d_in[12];
    float* out = (float*)d_out;

    const int GLU_SMEM = 36864 * 4;   // 147456
    const int STD_SMEM = 18688 * 4;   // 74752
    static int attr_done = 0;
    if (!attr_done) {
        cudaFuncSetAttribute(glu_mma_kernel, cudaFuncAttributeMaxDynamicSharedMemorySize, GLU_SMEM);
        cudaFuncSetAttribute(kproj_mma_kernel, cudaFuncAttributeMaxDynamicSharedMemorySize, STD_SMEM);
        cudaFuncSetAttribute(qproj_mma_kernel, cudaFuncAttributeMaxDynamicSharedMemorySize, STD_SMEM);
        cudaFuncSetAttribute(end_mma_kernel, cudaFuncAttributeMaxDynamicSharedMemorySize, STD_SMEM);
        attr_done = 1;
    }

    init_start_kernel<<<(START_SIZE + 255) / 256, 256>>>(out, ob);
    glu_mma_kernel<<<dim3(H3 / 128, M_ALL / 128), 256, GLU_SMEM>>>(hid, uw, ub, vw, vb, ow, out);
    kproj_mma_kernel<<<dim3(HD / 128, M_ALL / 128), 256, STD_SMEM>>>(hid, kw, kb);
    qproj_mma_kernel<<<dim3(HD / 128, BZ), 256, STD_SMEM>>>(hid, qw, qb, ent);
    end_mma_kernel<<<dim3(SQ / 128, BZ), 256, STD_SMEM>>>(mask, out);
}

// round 5
// speedup vs baseline: 2.7869x; 1.0968x over previous
#include <cuda_runtime.h>

// ---------------------------------------------------------------------------
// Problem constants
// ---------------------------------------------------------------------------
#define BZ   16
#define SQ   2048
#define HD   768
#define EZ   128
#define NTAG 10
#define H3   2304
#define M_ALL (BZ * SQ)            // 32768
#define START_SIZE (M_ALL * NTAG)  // 327680
#define INV96 (1.0f / 96.0f)
#define KTILES 24                  // 768 / 32

// Scratch
__device__ float g_k[M_ALL * HD];
__device__ float g_q[BZ * EZ * HD];

// ---------------------------------------------------------------------------
// PTX helpers (baseline compute_100: cp.async + mma.sync tf32)
// ---------------------------------------------------------------------------
__device__ __forceinline__ unsigned s2u(const void* p) {
    unsigned a;
    asm("{ .reg .u64 t; cvta.to.shared.u64 t, %1; cvt.u32.u64 %0, t; }"
        : "=r"(a) : "l"(p));
    return a;
}
__device__ __forceinline__ unsigned rna(float x) {
    unsigned r;
    asm("cvt.rna.tf32.f32 %0, %1;" : "=r"(r) : "f"(x));
    return r;
}
__device__ __forceinline__ float lds32(unsigned a) {
    float v;
    asm volatile("ld.shared.f32 %0, [%1];" : "=f"(v) : "r"(a));
    return v;
}
__device__ __forceinline__ void cpa16(unsigned d, const float* s) {
    asm volatile("cp.async.cg.shared.global [%0], [%1], 16;" :: "r"(d), "l"(s));
}
__device__ __forceinline__ void cpa_commit() {
    asm volatile("cp.async.commit_group;" ::: "memory");
}
__device__ __forceinline__ void cpa_wait1() {
    asm volatile("cp.async.wait_group 1;" ::: "memory");
}
__device__ __forceinline__ void mma8(float d[4], unsigned a0, unsigned a1,
                                     unsigned a2, unsigned a3,
                                     unsigned b0, unsigned b1) {
    asm volatile(
        "mma.sync.aligned.m16n8k8.row.col.f32.tf32.tf32.f32 "
        "{%0,%1,%2,%3}, {%4,%5,%6,%7}, {%8,%9}, {%0,%1,%2,%3};"
        : "+f"(d[0]), "+f"(d[1]), "+f"(d[2]), "+f"(d[3])
        : "r"(a0), "r"(a1), "r"(a2), "r"(a3), "r"(b0), "r"(b1));
}

#define ZERO_ACC(acc) \
    _Pragma("unroll") for (int _i = 0; _i < 4; ++_i) \
    _Pragma("unroll") for (int _j = 0; _j < 4; ++_j) \
    _Pragma("unroll") for (int _q = 0; _q < 4; ++_q) acc[_i][_j][_q] = 0.f;

// ---------------------------------------------------------------------------
// Core (single-B): C(128x128) += A(128x768).B(128x768)^T. 3-stage cp.async
// pipeline, one __syncthreads per k-tile. Stage = A[128][36]+B[128][36] floats
// (36864 B); 3 stages = 110592 B at smu.
// ---------------------------------------------------------------------------
__device__ __forceinline__ void gemm3s(
    unsigned smu,
    const float* a0, const float* a1, const float* a2, const float* a3,
    const float* b0,
    float acc[4][4][4], int tid)
{
    const int lane = tid & 31, warp = tid >> 5;
    const int wm = warp & 1, wn = warp >> 1;
    const int r = lane >> 2, cc = lane & 3;
    const unsigned dA = smu + (unsigned)(((tid >> 3) * 36 + (tid & 7) * 4) * 4);
    const float* asrc[4] = {a0, a1, a2, a3};

    unsigned aRow[4], bRow[4];
#pragma unroll
    for (int mi = 0; mi < 4; ++mi) aRow[mi] = (unsigned)((wm * 64 + mi * 16 + r) * 144);
#pragma unroll
    for (int ni = 0; ni < 4; ++ni) bRow[ni] = (unsigned)((wn * 32 + ni * 8 + r) * 144 + 18432);

    auto LOAD = [&](int kt) {
        unsigned off = (unsigned)(kt % 3) * 36864u;
        int ko = kt * 32;
#pragma unroll
        for (int j = 0; j < 4; ++j) {
            cpa16(dA + off + j * 4608u, asrc[j] + ko);
            cpa16(dA + off + 18432u + j * 4608u, b0 + (size_t)j * 32 * HD + ko);
        }
    };

    LOAD(0); cpa_commit();
    LOAD(1); cpa_commit();
    for (int kt = 0; kt < KTILES; ++kt) {
        cpa_wait1();
        __syncthreads();
        if (kt + 2 < KTILES) LOAD(kt + 2);
        cpa_commit();
        unsigned base = smu + (unsigned)(kt % 3) * 36864u;
#pragma unroll
        for (int k8 = 0; k8 < 4; ++k8) {
            unsigned ko = (unsigned)((k8 * 8 + cc) * 4);
            unsigned a[4][4];
#pragma unroll
            for (int mi = 0; mi < 4; ++mi) {
                unsigned p = base + aRow[mi] + ko;
                a[mi][0] = rna(lds32(p));
                a[mi][1] = rna(lds32(p + 8 * 144));
                a[mi][2] = rna(lds32(p + 16));
                a[mi][3] = rna(lds32(p + 8 * 144 + 16));
            }
#pragma unroll
            for (int ni = 0; ni < 4; ++ni) {
                unsigned p = base + bRow[ni] + ko;
                unsigned bb0 = rna(lds32(p)), bb1 = rna(lds32(p + 16));
#pragma unroll
                for (int mi = 0; mi < 4; ++mi)
                    mma8(acc[mi][ni], a[mi][0], a[mi][1], a[mi][2], a[mi][3], bb0, bb1);
            }
        }
    }
}

// ---------------------------------------------------------------------------
// Kernel 0: init start logits with o_b (GLU accumulates on top)
// ---------------------------------------------------------------------------
__global__ void init_start_kernel(float* __restrict__ out, const float* __restrict__ ob)
{
    int i = blockIdx.x * 256 + threadIdx.x;
    if (i < START_SIZE) out[i] = ob[i % NTAG];
}

// ---------------------------------------------------------------------------
// Kernel 1: fused GLU start head, SINGLE K-pass computing u and v together
// (A fragments shared by both MMAs), gate in registers, tag-reduce epilogue.
// Smem floats: [0,41472) pipeline 3 stages x (A+Bu+Bv each 4608);
// us 128x132 reuses [0,16896); ow_s at 41472, ub_s 42752, vb_s 42880.
// Total 43008 floats = 172032 B.
// ---------------------------------------------------------------------------
__global__ void __launch_bounds__(256) glu_mma_kernel(
    const float* __restrict__ hid,
    const float* __restrict__ uw, const float* __restrict__ ub,
    const float* __restrict__ vw, const float* __restrict__ vb,
    const float* __restrict__ ow,
    float* __restrict__ out)
{
    extern __shared__ float sm[];
    const unsigned smu = s2u(sm);
    float* us   = sm;                 // reuses pipeline region after mainloop
    float* ow_s = sm + 41472;
    float* ub_s = sm + 42752;
    float* vb_s = sm + 42880;

    const int tid = threadIdx.x;
    const int nb = blockIdx.x * 128, mb = blockIdx.y * 128;

    for (int i = tid; i < NTAG * 128; i += 256)
        ow_s[i] = ow[(i >> 7) * H3 + nb + (i & 127)];
    if (tid < 128) { ub_s[tid] = ub[nb + tid]; vb_s[tid] = vb[nb + tid]; }

    const int arow = tid >> 3, kch = tid & 7;
    const float* ha[4];
#pragma unroll
    for (int j = 0; j < 4; ++j)
        ha[j] = hid + (size_t)(mb + arow + 32 * j) * HD + kch * 4;
    const float* bu = uw + (size_t)(nb + arow) * HD + kch * 4;
    const float* bv = vw + (size_t)(nb + arow) * HD + kch * 4;

    const int lane = tid & 31, warp = tid >> 5;
    const int wm = warp & 1, wn = warp >> 1;
    const int r = lane >> 2, cc = lane & 3;
    const unsigned dA = smu + (unsigned)(((tid >> 3) * 36 + (tid & 7) * 4) * 4);

    unsigned aRow[4], bRow[4];
#pragma unroll
    for (int mi = 0; mi < 4; ++mi) aRow[mi] = (unsigned)((wm * 64 + mi * 16 + r) * 144);
#pragma unroll
    for (int ni = 0; ni < 4; ++ni) bRow[ni] = (unsigned)((wn * 32 + ni * 8 + r) * 144);

    auto LOAD = [&](int kt) {
        unsigned off = (unsigned)(kt % 3) * 55296u;   // stage stride: 3 tiles
        int ko = kt * 32;
#pragma unroll
        for (int j = 0; j < 4; ++j) {
            cpa16(dA + off + j * 4608u,           ha[j] + ko);
            cpa16(dA + off + 18432u + j * 4608u,  bu + (size_t)j * 32 * HD + ko);
            cpa16(dA + off + 36864u + j * 4608u,  bv + (size_t)j * 32 * HD + ko);
        }
    };

    float au[4][4][4], av[4][4][4];
    ZERO_ACC(au);
    ZERO_ACC(av);

    LOAD(0); cpa_commit();
    LOAD(1); cpa_commit();
    for (int kt = 0; kt < KTILES; ++kt) {
        cpa_wait1();
        __syncthreads();
        if (kt + 2 < KTILES) LOAD(kt + 2);
        cpa_commit();
        unsigned base = smu + (unsigned)(kt % 3) * 55296u;
#pragma unroll
        for (int k8 = 0; k8 < 4; ++k8) {
            unsigned ko = (unsigned)((k8 * 8 + cc) * 4);
            unsigned a[4][4];
#pragma unroll
            for (int mi = 0; mi < 4; ++mi) {
                unsigned p = base + aRow[mi] + ko;
                a[mi][0] = rna(lds32(p));
                a[mi][1] = rna(lds32(p + 8 * 144));
                a[mi][2] = rna(lds32(p + 16));
                a[mi][3] = rna(lds32(p + 8 * 144 + 16));
            }
#pragma unroll
            for (int ni = 0; ni < 4; ++ni) {
                unsigned pu = base + 18432u + bRow[ni] + ko;
                unsigned pv = base + 36864u + bRow[ni] + ko;
                unsigned u0 = rna(lds32(pu)), u1 = rna(lds32(pu + 16));
                unsigned v0 = rna(lds32(pv)), v1 = rna(lds32(pv + 16));
#pragma unroll
                for (int mi = 0; mi < 4; ++mi) {
                    mma8(au[mi][ni], a[mi][0], a[mi][1], a[mi][2], a[mi][3], u0, u1);
                    mma8(av[mi][ni], a[mi][0], a[mi][1], a[mi][2], a[mi][3], v0, v1);
                }
            }
        }
    }

    // gate in registers -> us (pipeline smem reused; safe: all threads past
    // final sync only read stage 2 [27648,41472), us occupies [0,16896))
#pragma unroll
    for (int mi = 0; mi < 4; ++mi) {
        int row = wm * 64 + mi * 16 + r;
#pragma unroll
        for (int ni = 0; ni < 4; ++ni) {
            int col = wn * 32 + ni * 8 + 2 * cc;
            float s0 = 1.f / (1.f + __expf(-(au[mi][ni][0] + ub_s[col])));
            float s1 = 1.f / (1.f + __expf(-(au[mi][ni][1] + ub_s[col + 1])));
            float s2 = 1.f / (1.f + __expf(-(au[mi][ni][2] + ub_s[col])));
            float s3 = 1.f / (1.f + __expf(-(au[mi][ni][3] + ub_s[col + 1])));
            us[row * 132 + col]           = s0 * (av[mi][ni][0] + vb_s[col]);
            us[row * 132 + col + 1]       = s1 * (av[mi][ni][1] + vb_s[col + 1]);
            us[(row + 8) * 132 + col]     = s2 * (av[mi][ni][2] + vb_s[col]);
            us[(row + 8) * 132 + col + 1] = s3 * (av[mi][ni][3] + vb_s[col + 1]);
        }
    }
    __syncthreads();

    // tag reduction + atomicAdd
    {
        const int row = tid & 127, half = tid >> 7;
        float t10[NTAG];
#pragma unroll
        for (int t = 0; t < NTAG; ++t) t10[t] = 0.f;
        const float* gr = us + row * 132 + half * 64;
        const float* owr = ow_s + half * 64;
#pragma unroll 4
        for (int n = 0; n < 64; ++n) {
            float g = gr[n];
#pragma unroll
            for (int t = 0; t < NTAG; ++t)
                t10[t] = fmaf(g, owr[t * 128 + n], t10[t]);
        }
        float* so = out + (size_t)(mb + row) * NTAG;
#pragma unroll
        for (int t = 0; t < NTAG; ++t) atomicAdd(so + t, t10[t]);
    }
}

// ---------------------------------------------------------------------------
// Kernel 2: k projection  g_k = hid @ kw^T + kb
// ---------------------------------------------------------------------------
__global__ void __launch_bounds__(256) kproj_mma_kernel(
    const float* __restrict__ hid, const float* __restrict__ kw,
    const float* __restrict__ kb)
{
    extern __shared__ float sm[];
    const unsigned smu = s2u(sm);
    float* kb_s = sm + 27648;
    const int tid = threadIdx.x;
    const int nb = blockIdx.x * 128, mb = blockIdx.y * 128;
    if (tid < 128) kb_s[tid] = kb[nb + tid];

    const int arow = tid >> 3, kch = tid & 7;
    const float* ha[4];
#pragma unroll
    for (int j = 0; j < 4; ++j)
        ha[j] = hid + (size_t)(mb + arow + 32 * j) * HD + kch * 4;
    const float* bk = kw + (size_t)(nb + arow) * HD + kch * 4;

    float acc[4][4][4];
    ZERO_ACC(acc);
    gemm3s(smu, ha[0], ha[1], ha[2], ha[3], bk, acc, tid);

    const int lane = tid & 31, warp = tid >> 5;
    const int wm = warp & 1, wn = warp >> 1;
    const int r = lane >> 2, cc = lane & 3;
#pragma unroll
    for (int mi = 0; mi < 4; ++mi) {
        int row = wm * 64 + mi * 16 + r;
#pragma unroll
        for (int ni = 0; ni < 4; ++ni) {
            int col = wn * 32 + ni * 8 + 2 * cc;
            float2 w0 = { acc[mi][ni][0] + kb_s[col], acc[mi][ni][1] + kb_s[col + 1] };
            float2 w1 = { acc[mi][ni][2] + kb_s[col], acc[mi][ni][3] + kb_s[col + 1] };
            *(float2*)(g_k + (size_t)(mb + row) * HD + nb + col) = w0;
            *(float2*)(g_k + (size_t)(mb + row + 8) * HD + nb + col) = w1;
        }
    }
}

// ---------------------------------------------------------------------------
// Kernel 3: gathered q projection (entity_start int32)
// ---------------------------------------------------------------------------
__global__ void __launch_bounds__(256) qproj_mma_kernel(
    const float* __restrict__ hid, const float* __restrict__ qw,
    const float* __restrict__ qb, const int* __restrict__ ent)
{
    extern __shared__ float sm[];
    const unsigned smu = s2u(sm);
    float* qb_s = sm + 27648;
    int* idxs = (int*)(sm + 27776);
    const int tid = threadIdx.x;
    const int nb = blockIdx.x * 128, b = blockIdx.y;
    if (tid < 128) { qb_s[tid] = qb[nb + tid]; idxs[tid] = ent[b * EZ + tid]; }
    __syncthreads();

    const int arow = tid >> 3, kch = tid & 7;
    const float* ha[4];
#pragma unroll
    for (int j = 0; j < 4; ++j)
        ha[j] = hid + ((size_t)b * SQ + idxs[arow + 32 * j]) * HD + kch * 4;
    const float* bq = qw + (size_t)(nb + arow) * HD + kch * 4;

    float acc[4][4][4];
    ZERO_ACC(acc);
    gemm3s(smu, ha[0], ha[1], ha[2], ha[3], bq, acc, tid);

    const int lane = tid & 31, warp = tid >> 5;
    const int wm = warp & 1, wn = warp >> 1;
    const int r = lane >> 2, cc = lane & 3;
#pragma unroll
    for (int mi = 0; mi < 4; ++mi) {
        int row = wm * 64 + mi * 16 + r;
#pragma unroll
        for (int ni = 0; ni < 4; ++ni) {
            int col = wn * 32 + ni * 8 + 2 * cc;
            float2 w0 = { acc[mi][ni][0] + qb_s[col], acc[mi][ni][1] + qb_s[col + 1] };
            float2 w1 = { acc[mi][ni][2] + qb_s[col], acc[mi][ni][3] + qb_s[col + 1] };
            *(float2*)(g_q + ((size_t)b * EZ + row) * HD + nb + col) = w0;
            *(float2*)(g_q + ((size_t)b * EZ + row + 8) * HD + nb + col) = w1;
        }
    }
}

// ---------------------------------------------------------------------------
// Kernel 4: end logits = (q . k)/96, masked (mask int32)
// ---------------------------------------------------------------------------
__global__ void __launch_bounds__(256) end_mma_kernel(
    const int* __restrict__ mask, float* __restrict__ out)
{
    extern __shared__ float sm[];
    const unsigned smu = s2u(sm);
    int* mask_s = (int*)(sm + 27648);
    const int tid = threadIdx.x;
    const int nb = blockIdx.x * 128, b = blockIdx.y;   // nb over S
    if (tid < 128) mask_s[tid] = mask[b * SQ + nb + tid];
    __syncthreads();

    const int arow = tid >> 3, kch = tid & 7;
    const float* ha[4];
#pragma unroll
    for (int j = 0; j < 4; ++j)
        ha[j] = g_q + ((size_t)b * EZ + arow + 32 * j) * HD + kch * 4;
    const float* bk = g_k + ((size_t)b * SQ + nb + arow) * HD + kch * 4;

    float acc[4][4][4];
    ZERO_ACC(acc);
    gemm3s(smu, ha[0], ha[1], ha[2], ha[3], bk, acc, tid);

    const int lane = tid & 31, warp = tid >> 5;
    const int wm = warp & 1, wn = warp >> 1;
    const int r = lane >> 2, cc = lane & 3;
    float* ob = out + START_SIZE + (size_t)b * EZ * SQ;
#pragma unroll
    for (int mi = 0; mi < 4; ++mi) {
        int row = wm * 64 + mi * 16 + r;
#pragma unroll
        for (int ni = 0; ni < 4; ++ni) {
            int col = wn * 32 + ni * 8 + 2 * cc;
            int m0 = mask_s[col], m1 = mask_s[col + 1];
            float2 w0 = { m0 ? acc[mi][ni][0] * INV96 : -50000.f,
                          m1 ? acc[mi][ni][1] * INV96 : -50000.f };
            float2 w1 = { m0 ? acc[mi][ni][2] * INV96 : -50000.f,
                          m1 ? acc[mi][ni][3] * INV96 : -50000.f };
            *(float2*)(ob + (size_t)row * SQ + nb + col) = w0;
            *(float2*)(ob + (size_t)(row + 8) * SQ + nb + col) = w1;
        }
    }
}

// ---------------------------------------------------------------------------
// Launch
// ---------------------------------------------------------------------------
extern "C" void kernel_launch(void* const* d_in, const int* in_sizes, int n_in,
                              void* d_out, int out_size)
{
    const float* hid  = (const float*)d_in[0];
    const float* uw   = (const float*)d_in[1];
    const float* ub   = (const float*)d_in[2];
    const float* vw   = (const float*)d_in[3];
    const float* vb   = (const float*)d_in[4];
    const float* ow   = (const float*)d_in[5];
    const float* ob   = (const float*)d_in[6];
    const float* qw   = (const float*)d_in[7];
    const float* qb   = (const float*)d_in[8];
    const float* kw   = (const float*)d_in[9];
    const float* kb   = (const float*)d_in[10];
    const int*   ent  = (const int*)d_in[11];
    const int*   mask = (const int*)d_in[12];
    float* out = (float*)d_out;

    const int GLU_SMEM = 43008 * 4;   // 172032
    const int STD_SMEM = 27904 * 4;   // 111616
    static int attr_done = 0;
    if (!attr_done) {
        cudaFuncSetAttribute(glu_mma_kernel, cudaFuncAttributeMaxDynamicSharedMemorySize, GLU_SMEM);
        cudaFuncSetAttribute(kproj_mma_kernel, cudaFuncAttributeMaxDynamicSharedMemorySize, STD_SMEM);
        cudaFuncSetAttribute(qproj_mma_kernel, cudaFuncAttributeMaxDynamicSharedMemorySize, STD_SMEM);
        cudaFuncSetAttribute(end_mma_kernel, cudaFuncAttributeMaxDynamicSharedMemorySize, STD_SMEM);
        attr_done = 1;
    }

    init_start_kernel<<<(START_SIZE + 255) / 256, 256>>>(out, ob);
    glu_mma_kernel<<<dim3(H3 / 128, M_ALL / 128), 256, GLU_SMEM>>>(hid, uw, ub, vw, vb, ow, out);
    kproj_mma_kernel<<<dim3(HD / 128, M_ALL / 128), 256, STD_SMEM>>>(hid, kw, kb);
    qproj_mma_kernel<<<dim3(HD / 128, BZ), 256, STD_SMEM>>>(hid, qw, qb, ent);
    end_mma_kernel<<<dim3(SQ / 128, BZ), 256, STD_SMEM>>>(mask, out);
}